// round 5
// baseline (speedup 1.0000x reference)
#include <cuda_runtime.h>
#include <cuda_bf16.h>
#include <mma.h>

using namespace nvcuda;

#define BATCH 256
#define TSTEPS 512
#define IDIM 256
#define HDIM 1024
#define KDIM 1280              // HDIM + IDIM
#define GROWS 4096             // 4*HDIM packed gate rows

// CTA tiling for the step GEMM
#define MT 64                  // batch tile
#define NT 128                 // packed gate-row tile (= 32 hidden units * 4 gates)
#define KC 64                  // K slab (fp32/tf32)
#define KCP 68                 // padded K stride in smem (fp32 elems, mult of 4)
#define GLD 132                // fp32 epilogue tile leading dim
#define NSLAB (KDIM / KC)      // 20
#define STAGE_ELEMS ((MT + NT) * KCP)          // 13056 floats
#define SMEM_BYTES (2 * STAGE_ELEMS * 4)       // 104448
#define NTHR 512

// ---------------- persistent device scratch (no allocations allowed) ---------
__device__ float g_Wpack[GROWS * KDIM];     // 21 MB, packed + tf32-rounded
__device__ float g_BiasPack[GROWS];
__device__ float g_HX[2][BATCH * KDIM];     // [h | x_t] ping-pong, tf32-rounded fp32
__device__ float g_C[BATCH * HDIM];         // cell state fp32 (full precision)

__device__ __forceinline__ float tf32r(float x) {
    asm("cvt.rna.tf32.f32 %0, %0;" : "+f"(x));
    return x;
}

__device__ __forceinline__ void cp_async16(void* sptr, const void* gptr) {
    unsigned sa = (unsigned)__cvta_generic_to_shared(sptr);
    asm volatile("cp.async.cg.shared.global [%0], [%1], 16;\n" :: "r"(sa), "l"(gptr));
}
__device__ __forceinline__ void cp_commit() {
    asm volatile("cp.async.commit_group;\n");
}
template <int N>
__device__ __forceinline__ void cp_wait() {
    asm volatile("cp.async.wait_group %0;\n" :: "n"(N));
}

// Pack [w_hh | w_ih] rows into per-CTA-contiguous order, tf32-round, fold biases.
// Packed row p = j*128 + gate*32 + r  <->  original gate row g = gate*1024 + j*32 + r
__global__ void k_convert(const float* __restrict__ w_ih, const float* __restrict__ w_hh,
                          const float* __restrict__ b_ih, const float* __restrict__ b_hh) {
    int total = GROWS * KDIM;
    for (int idx = blockIdx.x * blockDim.x + threadIdx.x; idx < total;
         idx += gridDim.x * blockDim.x) {
        int p = idx / KDIM, k = idx - p * KDIM;
        int j = p >> 7, gate = (p >> 5) & 3, r = p & 31;
        int g = gate * HDIM + j * 32 + r;
        float v = (k < HDIM) ? w_hh[g * HDIM + k] : w_ih[g * IDIM + (k - HDIM)];
        g_Wpack[idx] = tf32r(v);
        if (k == 0) g_BiasPack[p] = b_ih[g] + b_hh[g];
    }
}

// h=0, c=0, stage x_0 (tf32-rounded) into HX[0]
__global__ void k_init(const float* __restrict__ ts) {
    int idx = blockIdx.x * blockDim.x + threadIdx.x;
    if (idx >= BATCH * KDIM) return;
    int m = idx / KDIM, k = idx - m * KDIM;
    if (k < HDIM) {
        g_HX[0][idx] = 0.f;
        g_C[m * HDIM + k] = 0.f;
    } else {
        g_HX[0][idx] = tf32r(ts[m * (TSTEPS * IDIM) + (k - HDIM)]);
    }
}

__device__ __forceinline__ float sigmoidf_(float x) {
    return 1.f / (1.f + __expf(-x));
}

// One LSTM timestep: gates = HXr @ Wpack^T (tf32 wmma, 16 warps, 2-stage cp.async),
// fused cell update epilogue.
__global__ __launch_bounds__(NTHR, 1) void k_step(int t, const float* __restrict__ ts) {
    const float* __restrict__ HXr = g_HX[t & 1];
    float* __restrict__ HXw = g_HX[(t + 1) & 1];

    const int jt = blockIdx.x;        // 0..31  hidden-unit tile (32 units, 4 gates)
    const int mt = blockIdx.y;        // 0..3   batch tile
    const int m0 = mt * MT;
    const int p0 = jt * NT;

    extern __shared__ char smem[];
    float* Gs = (float*)smem;         // [MT][GLD] epilogue tile (aliases stage 0)

    const int tid = threadIdx.x;
    const int wid = tid >> 5;
    const int warp_m = wid & 3;       // 0..3 -> 16-row strip
    const int warp_n = wid >> 2;      // 0..3 -> 32-col strip

    wmma::fragment<wmma::accumulator, 16, 16, 8, float> acc[2];
    wmma::fill_fragment(acc[0], 0.f);
    wmma::fill_fragment(acc[1], 0.f);

    // ---- async load of one K slab into a stage: A 64x64, B 128x64 (float4s) ----
    auto load_slab = [&](int s, int stg) {
        float* As = (float*)smem + stg * STAGE_ELEMS;
        float* Bs = As + MT * KCP;
        int kc = s * KC;
        // A: 64 rows x 16 float4 = 1024 ops / 512 thr = 2 each
#pragma unroll
        for (int u = tid; u < MT * 16; u += NTHR) {
            int row = u >> 4, c4 = u & 15;
            cp_async16(As + row * KCP + c4 * 4,
                       HXr + (m0 + row) * KDIM + kc + c4 * 4);
        }
        // B: 128 rows x 16 float4 = 2048 ops / 512 thr = 4 each
#pragma unroll
        for (int u = tid; u < NT * 16; u += NTHR) {
            int row = u >> 4, c4 = u & 15;
            cp_async16(Bs + row * KCP + c4 * 4,
                       g_Wpack + (size_t)(p0 + row) * KDIM + kc + c4 * 4);
        }
    };

    load_slab(0, 0);
    cp_commit();

    for (int s = 0; s < NSLAB; ++s) {
        const int stg = s & 1;
        if (s + 1 < NSLAB) {
            load_slab(s + 1, stg ^ 1);
            cp_commit();
            cp_wait<1>();
        } else {
            cp_wait<0>();
        }
        __syncthreads();

        const float* As = (const float*)smem + stg * STAGE_ELEMS;
        const float* Bs = As + MT * KCP;
        const float* Arow = As + warp_m * 16 * KCP;
        const float* Brow0 = Bs + (warp_n * 32) * KCP;
        const float* Brow1 = Bs + (warp_n * 32 + 16) * KCP;

#pragma unroll
        for (int ko = 0; ko < KC; ko += 8) {
            wmma::fragment<wmma::matrix_a, 16, 16, 8, wmma::precision::tf32, wmma::row_major> af;
            wmma::fragment<wmma::matrix_b, 16, 16, 8, wmma::precision::tf32, wmma::col_major> bf0, bf1;
            wmma::load_matrix_sync(af, Arow + ko, KCP);
            wmma::load_matrix_sync(bf0, Brow0 + ko, KCP);
            wmma::load_matrix_sync(bf1, Brow1 + ko, KCP);
            wmma::mma_sync(acc[0], af, bf0, acc[0]);
            wmma::mma_sync(acc[1], af, bf1, acc[1]);
        }
        __syncthreads();
    }

    // spill gate tile to smem for the cross-gate epilogue
    wmma::store_matrix_sync(Gs + (warp_m * 16) * GLD + warp_n * 32, acc[0], GLD,
                            wmma::mem_row_major);
    wmma::store_matrix_sync(Gs + (warp_m * 16) * GLD + warp_n * 32 + 16, acc[1], GLD,
                            wmma::mem_row_major);
    __syncthreads();

    // fused LSTM cell update: 64 batch x 32 hidden units
    for (int q = tid; q < MT * 32; q += NTHR) {
        int ml = q >> 5, hh = q & 31;
        float il = Gs[ml * GLD + hh]      + g_BiasPack[p0 + hh];
        float fl = Gs[ml * GLD + 32 + hh] + g_BiasPack[p0 + 32 + hh];
        float gl = Gs[ml * GLD + 64 + hh] + g_BiasPack[p0 + 64 + hh];
        float ol = Gs[ml * GLD + 96 + hh] + g_BiasPack[p0 + 96 + hh];
        float ig = sigmoidf_(il);
        float fg = sigmoidf_(fl);
        float gt = tanhf(gl);
        float og = sigmoidf_(ol);
        int m = m0 + ml;
        int hcol = jt * 32 + hh;
        float c = fg * g_C[m * HDIM + hcol] + ig * gt;
        g_C[m * HDIM + hcol] = c;
        HXw[m * KDIM + hcol] = tf32r(og * tanhf(c));
    }

    // stage x_{t+1} (tf32-rounded) into the write buffer (CTAs jt<8 cover 256 cols)
    if (t + 1 < TSTEPS && jt < 8) {
        for (int q = tid; q < MT * 32; q += NTHR) {
            int ml = q >> 5, cc = q & 31;
            int m = m0 + ml;
            int col = jt * 32 + cc;
            HXw[m * KDIM + HDIM + col] = tf32r(ts[(m * TSTEPS + (t + 1)) * IDIM + col]);
        }
    }
}

// out[m] = c[m,:] . fc_w + fc_b
__global__ void k_fc(const float* __restrict__ fc_w, const float* __restrict__ fc_b,
                     float* __restrict__ out) {
    int m = blockIdx.x;
    float s = 0.f;
    for (int k = threadIdx.x; k < HDIM; k += blockDim.x)
        s += g_C[m * HDIM + k] * fc_w[k];
#pragma unroll
    for (int o = 16; o; o >>= 1) s += __shfl_xor_sync(0xffffffffu, s, o);
    __shared__ float red[32];
    if ((threadIdx.x & 31) == 0) red[threadIdx.x >> 5] = s;
    __syncthreads();
    if (threadIdx.x < 32) {
        float v = (threadIdx.x < (int)(blockDim.x >> 5)) ? red[threadIdx.x] : 0.f;
#pragma unroll
        for (int o = 16; o; o >>= 1) v += __shfl_xor_sync(0xffffffffu, v, o);
        if (threadIdx.x == 0) out[m] = v + fc_b[0];
    }
}

extern "C" void kernel_launch(void* const* d_in, const int* in_sizes, int n_in,
                              void* d_out, int out_size) {
    (void)in_sizes; (void)n_in; (void)out_size;
    const float* ts   = (const float*)d_in[0];
    const float* w_ih = (const float*)d_in[1];
    const float* w_hh = (const float*)d_in[2];
    const float* b_ih = (const float*)d_in[3];
    const float* b_hh = (const float*)d_in[4];
    const float* fc_w = (const float*)d_in[5];
    const float* fc_b = (const float*)d_in[6];
    float* out = (float*)d_out;

    // non-stream attribute call: safe under graph capture, idempotent
    cudaFuncSetAttribute(k_step, cudaFuncAttributeMaxDynamicSharedMemorySize, SMEM_BYTES);

    k_convert<<<512, 256>>>(w_ih, w_hh, b_ih, b_hh);
    k_init<<<(BATCH * KDIM + 255) / 256, 256>>>(ts);

    dim3 grid(32, 4);
    for (int t = 0; t < TSTEPS; ++t)
        k_step<<<grid, NTHR, SMEM_BYTES>>>(t, ts);

    k_fc<<<BATCH, 256>>>(fc_w, fc_b, out);
}

// round 6
// speedup vs baseline: 1.7921x; 1.7921x over previous
#include <cuda_runtime.h>
#include <cstdint>

#define BATCH 256
#define TSTEPS 512
#define IDIM 256
#define HDIM 1024
#define KDIM 1280              // HDIM + IDIM
#define GROWS 4096             // 4*HDIM packed gate rows
#define NKC (KDIM / 8)         // 160 k-chunks of 8

#define MT 64                  // batch tile per CTA
#define NT 128                 // gate cols per CTA (= 32 hidden units x 4 gates)
#define GLD 132                // epilogue smem tile leading dim
#define NTHR 512

// ---------------- persistent device scratch (no allocations allowed) ---------
// B in mma-fragment order: [(jt*4+wn)][kc][lane][nb*2+e]  (8 floats per lane)
__device__ float g_Wf[(size_t)GROWS * KDIM];
__device__ float g_BiasPack[GROWS];
// A (HX) in mma-fragment order: [(m>>4)][kc][lane][r]  (4 floats per lane), ping-pong
__device__ float g_HXf[2][BATCH * KDIM];
__device__ float g_C[BATCH * HDIM];         // cell state fp32 (linear)

__device__ __forceinline__ float tf32r(float x) {
    asm("cvt.rna.tf32.f32 %0, %0;" : "+f"(x));
    return x;
}
__device__ __forceinline__ float sigmoidf_(float x) { return 1.f / (1.f + __expf(-x)); }

// fragment index for A-side (HX) element (m, k):
// strip = m>>4 (16-row strips), kc = k>>3; lane/reg per mma.m16n8k8 A layout
__device__ __forceinline__ int frag_idx(int m, int k) {
    int rr = m & 15, kc = k >> 3, kk = k & 7;
    int lane = (rr & 7) * 4 + (kk & 3);
    int r = (rr >> 3) + 2 * (kk >> 2);
    return (((m >> 4) * NKC + kc) * 32 + lane) * 4 + r;
}

// m16n8k8 tf32 mma: D += A(16x8 row) x B(8x8 col)
__device__ __forceinline__ void mma8(float* c, float4 a, float bx, float by) {
    asm volatile(
        "mma.sync.aligned.m16n8k8.row.col.f32.tf32.tf32.f32 "
        "{%0,%1,%2,%3}, {%4,%5,%6,%7}, {%8,%9}, {%0,%1,%2,%3};"
        : "+f"(c[0]), "+f"(c[1]), "+f"(c[2]), "+f"(c[3])
        : "r"(__float_as_uint(a.x)), "r"(__float_as_uint(a.y)),
          "r"(__float_as_uint(a.z)), "r"(__float_as_uint(a.w)),
          "r"(__float_as_uint(bx)), "r"(__float_as_uint(by)));
}

// ------------------------------ setup kernels -------------------------------
// Fill g_Wf in B-fragment order + fold biases.
// dest float idx = ((strip*160 + kc)*32 + lane)*8 + nb*2 + e,  strip = jt*4 + gate
__global__ void k_convert(const float* __restrict__ w_ih, const float* __restrict__ w_hh,
                          const float* __restrict__ b_ih, const float* __restrict__ b_hh) {
    size_t total = (size_t)GROWS * KDIM;
    for (size_t idx = blockIdx.x * (size_t)blockDim.x + threadIdx.x; idx < total;
         idx += (size_t)gridDim.x * blockDim.x) {
        int e    = (int)(idx & 1);
        int nb   = (int)((idx >> 1) & 3);
        int lane = (int)((idx >> 3) & 31);
        int rest = (int)(idx >> 8);
        int kc = rest % NKC;
        int strip = rest / NKC;
        int gate = strip & 3, jt = strip >> 2;
        int hr = nb * 8 + (lane >> 2);            // n within 32-col strip
        int h = jt * 32 + hr;
        int g_row = gate * HDIM + h;
        int k = kc * 8 + (lane & 3) + e * 4;
        float v = (k < HDIM) ? w_hh[(size_t)g_row * HDIM + k]
                             : w_ih[(size_t)g_row * IDIM + (k - HDIM)];
        g_Wf[idx] = tf32r(v);
        if (kc == 0 && e == 0 && (lane & 3) == 0)
            g_BiasPack[jt * 128 + gate * 32 + hr] = b_ih[g_row] + b_hh[g_row];
    }
}

// h=0, c=0, stage x_0 (tf32) into fragment-ordered HX[0]
__global__ void k_init(const float* __restrict__ ts) {
    int idx = blockIdx.x * blockDim.x + threadIdx.x;
    if (idx >= BATCH * KDIM) return;
    int m = idx / KDIM, k = idx - m * KDIM;
    float v = 0.f;
    if (k < HDIM) {
        g_C[m * HDIM + k] = 0.f;
    } else {
        v = tf32r(ts[(size_t)m * (TSTEPS * IDIM) + (k - HDIM)]);
    }
    g_HXf[0][frag_idx(m, k)] = v;
}

// ------------------------------- LSTM timestep -------------------------------
// gates = HX @ Wpack^T via raw mma.m16n8k8, operands streamed LDG.128 from
// fragment-ordered global (no smem, no syncs in mainloop). Fused cell epilogue.
__global__ __launch_bounds__(NTHR, 1) void k_step(int t, const float* __restrict__ ts) {
    __shared__ float Gs[MT * GLD];   // 33792 B epilogue gate tile

    const float* __restrict__ HXr = g_HXf[t & 1];
    float* __restrict__ HXw = g_HXf[(t + 1) & 1];

    const int jt = blockIdx.x;        // 0..31  hidden-unit tile
    const int mt = blockIdx.y;        // 0..3   batch tile
    const int m0 = mt * MT;
    const int p0 = jt * NT;

    const int tid = threadIdx.x;
    const int wid = tid >> 5, lid = tid & 31;
    const int wm = wid & 3;           // 16-row strip within CTA tile
    const int wn = wid >> 2;          // = gate, 32-col strip

    // per-warp operand bases (float4 units)
    const float4* __restrict__ Ab =
        (const float4*)HXr + ((size_t)(mt * 4 + wm) * NKC) * 32 + lid;        // +32 per kc
    const float4* __restrict__ Bb =
        (const float4*)g_Wf + ((size_t)(jt * 4 + wn) * NKC) * 64 + lid * 2;   // +64 per kc

    float acc[4][4] = {};

#pragma unroll 4
    for (int kc = 0; kc < NKC; ++kc) {
        float4 a  = __ldg(Ab + (size_t)kc * 32);
        float4 b0 = __ldg(Bb + (size_t)kc * 64);
        float4 b1 = __ldg(Bb + (size_t)kc * 64 + 1);
        mma8(acc[0], a, b0.x, b0.y);
        mma8(acc[1], a, b0.z, b0.w);
        mma8(acc[2], a, b1.x, b1.y);
        mma8(acc[3], a, b1.z, b1.w);
    }

    // scatter acc to smem gate tile: row = wm*16 + lid/4 (+8), col = wn*32 + nb*8 + 2*(lid&3)
    {
        int row = wm * 16 + (lid >> 2);
        int col = wn * 32 + 2 * (lid & 3);
#pragma unroll
        for (int nb = 0; nb < 4; ++nb) {
            *(float2*)(Gs + row * GLD + col + nb * 8)       = make_float2(acc[nb][0], acc[nb][1]);
            *(float2*)(Gs + (row + 8) * GLD + col + nb * 8) = make_float2(acc[nb][2], acc[nb][3]);
        }
    }
    __syncthreads();

    // fused LSTM cell update: 64 batch rows x 32 hidden units
    for (int q = tid; q < MT * 32; q += NTHR) {
        int ml = q >> 5, hh = q & 31;
        float il = Gs[ml * GLD + hh]      + g_BiasPack[p0 + hh];
        float fl = Gs[ml * GLD + 32 + hh] + g_BiasPack[p0 + 32 + hh];
        float gl = Gs[ml * GLD + 64 + hh] + g_BiasPack[p0 + 64 + hh];
        float ol = Gs[ml * GLD + 96 + hh] + g_BiasPack[p0 + 96 + hh];
        float ig = sigmoidf_(il);
        float fg = sigmoidf_(fl);
        float gt = tanhf(gl);
        float og = sigmoidf_(ol);
        int m = m0 + ml;
        int hcol = jt * 32 + hh;
        float c = fg * g_C[m * HDIM + hcol] + ig * gt;
        g_C[m * HDIM + hcol] = c;
        HXw[frag_idx(m, hcol)] = tf32r(og * tanhf(c));
    }

    // stage x_{t+1} into fragment order (CTAs jt<8 cover the 256 input cols)
    if (t + 1 < TSTEPS && jt < 8) {
        for (int q = tid; q < MT * 32; q += NTHR) {
            int ml = q >> 5, cc = q & 31;
            int m = m0 + ml;
            int k = HDIM + jt * 32 + cc;
            float v = tf32r(ts[((size_t)m * TSTEPS + (t + 1)) * IDIM + jt * 32 + cc]);
            HXw[frag_idx(m, k)] = v;
        }
    }
}

// out[m] = c[m,:] . fc_w + fc_b
__global__ void k_fc(const float* __restrict__ fc_w, const float* __restrict__ fc_b,
                     float* __restrict__ out) {
    int m = blockIdx.x;
    float s = 0.f;
    for (int k = threadIdx.x; k < HDIM; k += blockDim.x)
        s += g_C[m * HDIM + k] * fc_w[k];
#pragma unroll
    for (int o = 16; o; o >>= 1) s += __shfl_xor_sync(0xffffffffu, s, o);
    __shared__ float red[32];
    if ((threadIdx.x & 31) == 0) red[threadIdx.x >> 5] = s;
    __syncthreads();
    if (threadIdx.x < 32) {
        float v = (threadIdx.x < (int)(blockDim.x >> 5)) ? red[threadIdx.x] : 0.f;
#pragma unroll
        for (int o = 16; o; o >>= 1) v += __shfl_xor_sync(0xffffffffu, v, o);
        if (threadIdx.x == 0) out[m] = v + fc_b[0];
    }
}

extern "C" void kernel_launch(void* const* d_in, const int* in_sizes, int n_in,
                              void* d_out, int out_size) {
    (void)in_sizes; (void)n_in; (void)out_size;
    const float* ts   = (const float*)d_in[0];
    const float* w_ih = (const float*)d_in[1];
    const float* w_hh = (const float*)d_in[2];
    const float* b_ih = (const float*)d_in[3];
    const float* b_hh = (const float*)d_in[4];
    const float* fc_w = (const float*)d_in[5];
    const float* fc_b = (const float*)d_in[6];
    float* out = (float*)d_out;

    k_convert<<<512, 256>>>(w_ih, w_hh, b_ih, b_hh);
    k_init<<<(BATCH * KDIM + 255) / 256, 256>>>(ts);

    dim3 grid(32, 4);
    for (int t = 0; t < TSTEPS; ++t)
        k_step<<<grid, NTHR>>>(t, ts);

    k_fc<<<BATCH, 256>>>(fc_w, fc_b, out);
}

// round 7
// speedup vs baseline: 1.9357x; 1.0801x over previous
#include <cuda_runtime.h>
#include <cstdint>

#define BATCH 256
#define TSTEPS 512
#define IDIM 256
#define HDIM 1024
#define KDIM 1280              // HDIM + IDIM
#define GROWS 4096             // 4*HDIM packed gate rows
#define NKC (KDIM / 8)         // 160 k-chunks of 8

#define MT 64                  // batch tile per CTA
#define NT 128                 // gate cols per CTA (= 32 hidden units x 4 gates)
#define GLD 132                // epilogue smem tile leading dim
#define NTHR 256               // 8 warps: warp tile 32(M) x 32(N)

// ---------------- persistent device scratch (no allocations allowed) ---------
// B in mma-fragment order: [(jt*4+wn)][kc][lane][nb*2+e]  (8 floats per lane)
__device__ float g_Wf[(size_t)GROWS * KDIM];
__device__ float g_BiasPack[GROWS];
// A (HX) in mma-fragment order: [(m>>4)][kc][lane][r]  (4 floats per lane), ping-pong
__device__ float g_HXf[2][BATCH * KDIM];
__device__ float g_C[BATCH * HDIM];         // cell state fp32 (linear)

__device__ __forceinline__ float tf32r(float x) {
    asm("cvt.rna.tf32.f32 %0, %0;" : "+f"(x));
    return x;
}
__device__ __forceinline__ float sigmoidf_(float x) { return 1.f / (1.f + __expf(-x)); }

// fragment index for A-side (HX) element (m, k):
// strip = m>>4 (16-row strips), kc = k>>3; lane/reg per mma.m16n8k8 A layout
__device__ __forceinline__ int frag_idx(int m, int k) {
    int rr = m & 15, kc = k >> 3, kk = k & 7;
    int lane = (rr & 7) * 4 + (kk & 3);
    int r = (rr >> 3) + 2 * (kk >> 2);
    return (((m >> 4) * NKC + kc) * 32 + lane) * 4 + r;
}

// m16n8k8 tf32 mma: D += A(16x8 row) x B(8x8 col)
__device__ __forceinline__ void mma8(float* c, float4 a, float bx, float by) {
    asm volatile(
        "mma.sync.aligned.m16n8k8.row.col.f32.tf32.tf32.f32 "
        "{%0,%1,%2,%3}, {%4,%5,%6,%7}, {%8,%9}, {%0,%1,%2,%3};"
        : "+f"(c[0]), "+f"(c[1]), "+f"(c[2]), "+f"(c[3])
        : "r"(__float_as_uint(a.x)), "r"(__float_as_uint(a.y)),
          "r"(__float_as_uint(a.z)), "r"(__float_as_uint(a.w)),
          "r"(__float_as_uint(bx)), "r"(__float_as_uint(by)));
}

// ------------------------------ setup kernels -------------------------------
// Fill g_Wf in B-fragment order + fold biases.
// dest float idx = ((strip*160 + kc)*32 + lane)*8 + nb*2 + e,  strip = jt*4 + gate
__global__ void k_convert(const float* __restrict__ w_ih, const float* __restrict__ w_hh,
                          const float* __restrict__ b_ih, const float* __restrict__ b_hh) {
    size_t total = (size_t)GROWS * KDIM;
    for (size_t idx = blockIdx.x * (size_t)blockDim.x + threadIdx.x; idx < total;
         idx += (size_t)gridDim.x * blockDim.x) {
        int e    = (int)(idx & 1);
        int nb   = (int)((idx >> 1) & 3);
        int lane = (int)((idx >> 3) & 31);
        int rest = (int)(idx >> 8);
        int kc = rest % NKC;
        int strip = rest / NKC;
        int gate = strip & 3, jt = strip >> 2;
        int hr = nb * 8 + (lane >> 2);            // n within 32-col strip
        int h = jt * 32 + hr;
        int g_row = gate * HDIM + h;
        int k = kc * 8 + (lane & 3) + e * 4;
        float v = (k < HDIM) ? w_hh[(size_t)g_row * HDIM + k]
                             : w_ih[(size_t)g_row * IDIM + (k - HDIM)];
        g_Wf[idx] = tf32r(v);
        if (kc == 0 && e == 0 && (lane & 3) == 0)
            g_BiasPack[jt * 128 + gate * 32 + hr] = b_ih[g_row] + b_hh[g_row];
    }
}

// h=0, c=0, stage x_0 (tf32) into fragment-ordered HX[0]
__global__ void k_init(const float* __restrict__ ts) {
    int idx = blockIdx.x * blockDim.x + threadIdx.x;
    if (idx >= BATCH * KDIM) return;
    int m = idx / KDIM, k = idx - m * KDIM;
    float v = 0.f;
    if (k < HDIM) {
        g_C[m * HDIM + k] = 0.f;
    } else {
        v = tf32r(ts[(size_t)m * (TSTEPS * IDIM) + (k - HDIM)]);
    }
    g_HXf[0][frag_idx(m, k)] = v;
}

// ------------------------------- LSTM timestep -------------------------------
// gates = HX @ Wpack^T via raw mma.m16n8k8, warp tile 32x32, operands streamed
// LDG.128 from fragment-ordered global (no smem/syncs in mainloop). Fused epilogue.
__global__ __launch_bounds__(NTHR, 1) void k_step(int t, const float* __restrict__ ts) {
    __shared__ float Gs[MT * GLD];   // 33792 B epilogue gate tile

    const float* __restrict__ HXr = g_HXf[t & 1];
    float* __restrict__ HXw = g_HXf[(t + 1) & 1];

    const int jt = blockIdx.x;        // 0..31  hidden-unit tile
    const int mt = blockIdx.y;        // 0..3   batch tile
    const int m0 = mt * MT;
    const int p0 = jt * NT;

    const int tid = threadIdx.x;
    const int wid = tid >> 5, lid = tid & 31;
    const int wm = wid & 1;           // 32-row half within CTA tile
    const int wn = wid >> 1;          // 0..3 -> 32-col strip (= gate)

    // per-warp operand bases (float4 units)
    const float4* __restrict__ Ab0 =
        (const float4*)HXr + ((size_t)(mt * 4 + wm * 2) * NKC) * 32 + lid;    // strip 0
    const float4* __restrict__ Ab1 = Ab0 + (size_t)NKC * 32;                   // strip 1
    const float4* __restrict__ Bb =
        (const float4*)g_Wf + ((size_t)(jt * 4 + wn) * NKC) * 64 + lid * 2;

    float acc[2][4][4] = {};

#pragma unroll 4
    for (int kc = 0; kc < NKC; ++kc) {
        float4 a0 = __ldg(Ab0 + (size_t)kc * 32);
        float4 a1 = __ldg(Ab1 + (size_t)kc * 32);
        float4 b0 = __ldg(Bb + (size_t)kc * 64);
        float4 b1 = __ldg(Bb + (size_t)kc * 64 + 1);
        mma8(acc[0][0], a0, b0.x, b0.y);
        mma8(acc[1][0], a1, b0.x, b0.y);
        mma8(acc[0][1], a0, b0.z, b0.w);
        mma8(acc[1][1], a1, b0.z, b0.w);
        mma8(acc[0][2], a0, b1.x, b1.y);
        mma8(acc[1][2], a1, b1.x, b1.y);
        mma8(acc[0][3], a0, b1.z, b1.w);
        mma8(acc[1][3], a1, b1.z, b1.w);
    }

    // scatter acc to smem gate tile:
    // row = wm*32 + i*16 + lid/4 (+8), col = wn*32 + nb*8 + 2*(lid&3)
    {
        int row = wm * 32 + (lid >> 2);
        int col = wn * 32 + 2 * (lid & 3);
#pragma unroll
        for (int i = 0; i < 2; ++i) {
#pragma unroll
            for (int nb = 0; nb < 4; ++nb) {
                *(float2*)(Gs + (row + i * 16) * GLD + col + nb * 8) =
                    make_float2(acc[i][nb][0], acc[i][nb][1]);
                *(float2*)(Gs + (row + i * 16 + 8) * GLD + col + nb * 8) =
                    make_float2(acc[i][nb][2], acc[i][nb][3]);
            }
        }
    }
    __syncthreads();

    // fused LSTM cell update: 64 batch rows x 32 hidden units
    for (int q = tid; q < MT * 32; q += NTHR) {
        int ml = q >> 5, hh = q & 31;
        float il = Gs[ml * GLD + hh]      + g_BiasPack[p0 + hh];
        float fl = Gs[ml * GLD + 32 + hh] + g_BiasPack[p0 + 32 + hh];
        float gl = Gs[ml * GLD + 64 + hh] + g_BiasPack[p0 + 64 + hh];
        float ol = Gs[ml * GLD + 96 + hh] + g_BiasPack[p0 + 96 + hh];
        float ig = sigmoidf_(il);
        float fg = sigmoidf_(fl);
        float gt = tanhf(gl);
        float og = sigmoidf_(ol);
        int m = m0 + ml;
        int hcol = jt * 32 + hh;
        float c = fg * g_C[m * HDIM + hcol] + ig * gt;
        g_C[m * HDIM + hcol] = c;
        HXw[frag_idx(m, hcol)] = tf32r(og * tanhf(c));
    }

    // stage x_{t+1} into fragment order (CTAs jt<8 cover the 256 input cols)
    if (t + 1 < TSTEPS && jt < 8) {
        for (int q = tid; q < MT * 32; q += NTHR) {
            int ml = q >> 5, cc = q & 31;
            int m = m0 + ml;
            int k = HDIM + jt * 32 + cc;
            float v = tf32r(ts[((size_t)m * TSTEPS + (t + 1)) * IDIM + jt * 32 + cc]);
            HXw[frag_idx(m, k)] = v;
        }
    }
}

// out[m] = c[m,:] . fc_w + fc_b
__global__ void k_fc(const float* __restrict__ fc_w, const float* __restrict__ fc_b,
                     float* __restrict__ out) {
    int m = blockIdx.x;
    float s = 0.f;
    for (int k = threadIdx.x; k < HDIM; k += blockDim.x)
        s += g_C[m * HDIM + k] * fc_w[k];
#pragma unroll
    for (int o = 16; o; o >>= 1) s += __shfl_xor_sync(0xffffffffu, s, o);
    __shared__ float red[32];
    if ((threadIdx.x & 31) == 0) red[threadIdx.x >> 5] = s;
    __syncthreads();
    if (threadIdx.x < 32) {
        float v = (threadIdx.x < (int)(blockDim.x >> 5)) ? red[threadIdx.x] : 0.f;
#pragma unroll
        for (int o = 16; o; o >>= 1) v += __shfl_xor_sync(0xffffffffu, v, o);
        if (threadIdx.x == 0) out[m] = v + fc_b[0];
    }
}

extern "C" void kernel_launch(void* const* d_in, const int* in_sizes, int n_in,
                              void* d_out, int out_size) {
    (void)in_sizes; (void)n_in; (void)out_size;
    const float* ts   = (const float*)d_in[0];
    const float* w_ih = (const float*)d_in[1];
    const float* w_hh = (const float*)d_in[2];
    const float* b_ih = (const float*)d_in[3];
    const float* b_hh = (const float*)d_in[4];
    const float* fc_w = (const float*)d_in[5];
    const float* fc_b = (const float*)d_in[6];
    float* out = (float*)d_out;

    k_convert<<<512, 256>>>(w_ih, w_hh, b_ih, b_hh);
    k_init<<<(BATCH * KDIM + 255) / 256, 256>>>(ts);

    dim3 grid(32, 4);
    for (int t = 0; t < TSTEPS; ++t)
        k_step<<<grid, NTHR>>>(t, ts);

    k_fc<<<BATCH, 256>>>(fc_w, fc_b, out);
}

// round 8
// speedup vs baseline: 2.5502x; 1.3175x over previous
#include <cuda_runtime.h>
#include <cstdint>

#define BATCH 256
#define TSTEPS 512
#define IDIM 256
#define HDIM 1024
#define KDIM 1280              // HDIM + IDIM
#define GROWS 4096             // 4*HDIM packed gate rows
#define NKC (KDIM / 8)         // 160 k-chunks of 8
#define NKH (NKC / 2)          // 80 per K-half

#define MT 64                  // batch tile per CTA
#define NT 128                 // gate cols per CTA (= 32 hidden units x 4 gates)
#define GLD 132                // epilogue smem tile leading dim
#define NTHR 512               // 16 warps: (wm,wn) 32x32 tile x kh K-half

// ---------------- persistent device scratch (no allocations allowed) ---------
// B in mma-fragment order: [(jt*4+wn)][kc][lane][nb*2+e]  (8 floats per lane)
__device__ float g_Wf[(size_t)GROWS * KDIM];
__device__ float g_BiasPack[GROWS];
// A (HX) in mma-fragment order: [(m>>4)][kc][lane][r]  (4 floats per lane), ping-pong
__device__ float g_HXf[2][BATCH * KDIM];
__device__ float g_C[BATCH * HDIM];         // cell state fp32 (linear)

__device__ __forceinline__ float tf32r(float x) {
    asm("cvt.rna.tf32.f32 %0, %0;" : "+f"(x));
    return x;
}
__device__ __forceinline__ float sigmoidf_(float x) { return 1.f / (1.f + __expf(-x)); }

// fragment index for A-side (HX) element (m, k)
__device__ __forceinline__ int frag_idx(int m, int k) {
    int rr = m & 15, kc = k >> 3, kk = k & 7;
    int lane = (rr & 7) * 4 + (kk & 3);
    int r = (rr >> 3) + 2 * (kk >> 2);
    return (((m >> 4) * NKC + kc) * 32 + lane) * 4 + r;
}

// m16n8k8 tf32 mma: D += A(16x8 row) x B(8x8 col)
__device__ __forceinline__ void mma8(float* c, float4 a, float bx, float by) {
    asm volatile(
        "mma.sync.aligned.m16n8k8.row.col.f32.tf32.tf32.f32 "
        "{%0,%1,%2,%3}, {%4,%5,%6,%7}, {%8,%9}, {%0,%1,%2,%3};"
        : "+f"(c[0]), "+f"(c[1]), "+f"(c[2]), "+f"(c[3])
        : "r"(__float_as_uint(a.x)), "r"(__float_as_uint(a.y)),
          "r"(__float_as_uint(a.z)), "r"(__float_as_uint(a.w)),
          "r"(__float_as_uint(bx)), "r"(__float_as_uint(by)));
}

// ------------------------------ setup kernels -------------------------------
__global__ void k_convert(const float* __restrict__ w_ih, const float* __restrict__ w_hh,
                          const float* __restrict__ b_ih, const float* __restrict__ b_hh) {
    size_t total = (size_t)GROWS * KDIM;
    for (size_t idx = blockIdx.x * (size_t)blockDim.x + threadIdx.x; idx < total;
         idx += (size_t)gridDim.x * blockDim.x) {
        int e    = (int)(idx & 1);
        int nb   = (int)((idx >> 1) & 3);
        int lane = (int)((idx >> 3) & 31);
        int rest = (int)(idx >> 8);
        int kc = rest % NKC;
        int strip = rest / NKC;
        int gate = strip & 3, jt = strip >> 2;
        int hr = nb * 8 + (lane >> 2);
        int h = jt * 32 + hr;
        int g_row = gate * HDIM + h;
        int k = kc * 8 + (lane & 3) + e * 4;
        float v = (k < HDIM) ? w_hh[(size_t)g_row * HDIM + k]
                             : w_ih[(size_t)g_row * IDIM + (k - HDIM)];
        g_Wf[idx] = tf32r(v);
        if (kc == 0 && e == 0 && (lane & 3) == 0)
            g_BiasPack[jt * 128 + gate * 32 + hr] = b_ih[g_row] + b_hh[g_row];
    }
}

__global__ void k_init(const float* __restrict__ ts) {
    int idx = blockIdx.x * blockDim.x + threadIdx.x;
    if (idx >= BATCH * KDIM) return;
    int m = idx / KDIM, k = idx - m * KDIM;
    float v = 0.f;
    if (k < HDIM) {
        g_C[m * HDIM + k] = 0.f;
    } else {
        v = tf32r(ts[(size_t)m * (TSTEPS * IDIM) + (k - HDIM)]);
    }
    g_HXf[0][frag_idx(m, k)] = v;
}

// ------------------------------- LSTM timestep -------------------------------
// gates = HX @ Wpack^T via raw mma.m16n8k8, warp tile 32x32, K split over warp
// pairs, distance-1 register prefetch. Fused cell epilogue.
__global__ __launch_bounds__(NTHR, 1) void k_step(int t, const float* __restrict__ ts) {
    __shared__ float Gs[MT * GLD];   // 33792 B epilogue gate tile

    const float* __restrict__ HXr = g_HXf[t & 1];
    float* __restrict__ HXw = g_HXf[(t + 1) & 1];

    const int jt = blockIdx.x;        // 0..31
    const int mt = blockIdx.y;        // 0..3
    const int m0 = mt * MT;
    const int p0 = jt * NT;

    const int tid = threadIdx.x;
    const int wid = tid >> 5, lid = tid & 31;
    const int kh = wid >> 3;          // 0,1 -> K half
    const int wm = wid & 1;           // 32-row half
    const int wn = (wid >> 1) & 3;    // 32-col strip (= gate)

    const int kc0 = kh * NKH;
    const float4* __restrict__ Ab0 =
        (const float4*)HXr + ((size_t)(mt * 4 + wm * 2) * NKC + kc0) * 32 + lid;
    const float4* __restrict__ Ab1 = Ab0 + (size_t)NKC * 32;
    const float4* __restrict__ Bb =
        (const float4*)g_Wf + ((size_t)(jt * 4 + wn) * NKC + kc0) * 64 + lid * 2;

    float acc[2][4][4] = {};

    float4 a0 = __ldg(Ab0);
    float4 a1 = __ldg(Ab1);
    float4 b0 = __ldg(Bb);
    float4 b1 = __ldg(Bb + 1);

#pragma unroll 4
    for (int i = 0; i < NKH - 1; ++i) {
        float4 na0 = __ldg(Ab0 + (size_t)(i + 1) * 32);
        float4 na1 = __ldg(Ab1 + (size_t)(i + 1) * 32);
        float4 nb0 = __ldg(Bb + (size_t)(i + 1) * 64);
        float4 nb1 = __ldg(Bb + (size_t)(i + 1) * 64 + 1);
        mma8(acc[0][0], a0, b0.x, b0.y);
        mma8(acc[1][0], a1, b0.x, b0.y);
        mma8(acc[0][1], a0, b0.z, b0.w);
        mma8(acc[1][1], a1, b0.z, b0.w);
        mma8(acc[0][2], a0, b1.x, b1.y);
        mma8(acc[1][2], a1, b1.x, b1.y);
        mma8(acc[0][3], a0, b1.z, b1.w);
        mma8(acc[1][3], a1, b1.z, b1.w);
        a0 = na0; a1 = na1; b0 = nb0; b1 = nb1;
    }
    mma8(acc[0][0], a0, b0.x, b0.y);
    mma8(acc[1][0], a1, b0.x, b0.y);
    mma8(acc[0][1], a0, b0.z, b0.w);
    mma8(acc[1][1], a1, b0.z, b0.w);
    mma8(acc[0][2], a0, b1.x, b1.y);
    mma8(acc[1][2], a1, b1.x, b1.y);
    mma8(acc[0][3], a0, b1.z, b1.w);
    mma8(acc[1][3], a1, b1.z, b1.w);

    // reduce the two K-halves into the smem gate tile
    const int row = wm * 32 + (lid >> 2);
    const int col = wn * 32 + 2 * (lid & 3);
    if (kh == 0) {
#pragma unroll
        for (int i = 0; i < 2; ++i)
#pragma unroll
            for (int nb = 0; nb < 4; ++nb) {
                *(float2*)(Gs + (row + i * 16) * GLD + col + nb * 8) =
                    make_float2(acc[i][nb][0], acc[i][nb][1]);
                *(float2*)(Gs + (row + i * 16 + 8) * GLD + col + nb * 8) =
                    make_float2(acc[i][nb][2], acc[i][nb][3]);
            }
    }
    __syncthreads();
    if (kh == 1) {
#pragma unroll
        for (int i = 0; i < 2; ++i)
#pragma unroll
            for (int nb = 0; nb < 4; ++nb) {
                float2* p0v = (float2*)(Gs + (row + i * 16) * GLD + col + nb * 8);
                float2* p1v = (float2*)(Gs + (row + i * 16 + 8) * GLD + col + nb * 8);
                float2 v0 = *p0v, v1 = *p1v;
                v0.x += acc[i][nb][0]; v0.y += acc[i][nb][1];
                v1.x += acc[i][nb][2]; v1.y += acc[i][nb][3];
                *p0v = v0; *p1v = v1;
            }
    }
    __syncthreads();

    // fused LSTM cell update: 64 batch rows x 32 hidden units
    for (int q = tid; q < MT * 32; q += NTHR) {
        int ml = q >> 5, hh = q & 31;
        float il = Gs[ml * GLD + hh]      + g_BiasPack[p0 + hh];
        float fl = Gs[ml * GLD + 32 + hh] + g_BiasPack[p0 + 32 + hh];
        float gl = Gs[ml * GLD + 64 + hh] + g_BiasPack[p0 + 64 + hh];
        float ol = Gs[ml * GLD + 96 + hh] + g_BiasPack[p0 + 96 + hh];
        float ig = sigmoidf_(il);
        float fg = sigmoidf_(fl);
        float gt = tanhf(gl);
        float og = sigmoidf_(ol);
        int m = m0 + ml;
        int hcol = jt * 32 + hh;
        float c = fg * g_C[m * HDIM + hcol] + ig * gt;
        g_C[m * HDIM + hcol] = c;
        HXw[frag_idx(m, hcol)] = tf32r(og * tanhf(c));
    }

    // stage x_{t+1} into fragment order (CTAs jt<8 cover the 256 input cols)
    if (t + 1 < TSTEPS && jt < 8) {
        for (int q = tid; q < MT * 32; q += NTHR) {
            int ml = q >> 5, cc = q & 31;
            int m = m0 + ml;
            int k = HDIM + jt * 32 + cc;
            float v = tf32r(ts[((size_t)m * TSTEPS + (t + 1)) * IDIM + jt * 32 + cc]);
            HXw[frag_idx(m, k)] = v;
        }
    }
}

// out[m] = c[m,:] . fc_w + fc_b
__global__ void k_fc(const float* __restrict__ fc_w, const float* __restrict__ fc_b,
                     float* __restrict__ out) {
    int m = blockIdx.x;
    float s = 0.f;
    for (int k = threadIdx.x; k < HDIM; k += blockDim.x)
        s += g_C[m * HDIM + k] * fc_w[k];
#pragma unroll
    for (int o = 16; o; o >>= 1) s += __shfl_xor_sync(0xffffffffu, s, o);
    __shared__ float red[32];
    if ((threadIdx.x & 31) == 0) red[threadIdx.x >> 5] = s;
    __syncthreads();
    if (threadIdx.x < 32) {
        float v = (threadIdx.x < (int)(blockDim.x >> 5)) ? red[threadIdx.x] : 0.f;
#pragma unroll
        for (int o = 16; o; o >>= 1) v += __shfl_xor_sync(0xffffffffu, v, o);
        if (threadIdx.x == 0) out[m] = v + fc_b[0];
    }
}

extern "C" void kernel_launch(void* const* d_in, const int* in_sizes, int n_in,
                              void* d_out, int out_size) {
    (void)in_sizes; (void)n_in; (void)out_size;
    const float* ts   = (const float*)d_in[0];
    const float* w_ih = (const float*)d_in[1];
    const float* w_hh = (const float*)d_in[2];
    const float* b_ih = (const float*)d_in[3];
    const float* b_hh = (const float*)d_in[4];
    const float* fc_w = (const float*)d_in[5];
    const float* fc_b = (const float*)d_in[6];
    float* out = (float*)d_out;

    k_convert<<<512, 256>>>(w_ih, w_hh, b_ih, b_hh);
    k_init<<<(BATCH * KDIM + 255) / 256, 256>>>(ts);

    dim3 grid(32, 4);
    for (int t = 0; t < TSTEPS; ++t)
        k_step<<<grid, NTHR>>>(t, ts);

    k_fc<<<BATCH, 256>>>(fc_w, fc_b, out);
}